// round 7
// baseline (speedup 1.0000x reference)
#include <cuda_runtime.h>
#include <math.h>

// SpikingLayer T=500, B*N=65536. Fused single kernel, 2 neurons/thread (float2).
// Per 32-step group: build packed spike words from loaded floats, keep rolling
// 6-word history in registers; lag-50/100 taps via funnel composites; exact
// near-threshold recompute runs from register words (reference f32 rounding:
// sum k[j] over set bits, lag j descending 148..0, sequential f32 adds).
// Decision logic identical to R3-R6 passing kernels (bit-stable).

#define TBN 65536
#define HTBN (TBN / 2)
#define T_STEPS 500
#define MARGIN 1e-3f
#define BLK 128

__device__ __forceinline__ float exact_vmem_w(const unsigned W[6], int i,
                                              const float* __restrict__ ks) {
    // W[k] = packed word of group g-k (bit p = x[32*(g-k)+p]); t = 32g + i.
    float acc = 0.0f;
    #pragma unroll
    for (int w = 4; w >= 0; w--) {                 // oldest lag window first
        unsigned win = __funnelshift_rc(W[w + 1], W[w], (unsigned)(i + 1));
        unsigned m = __brev(win);                  // bit b = x[t - 32w - b]
        if (w == 4) m &= 0x001FFFFFu;              // lags <= 148
        while (m) {                                // descending lag order
            unsigned b = 31u - __clz(m);
            acc += ks[32 * w + b];
            m &= ~(1u << b);
        }
    }
    return acc;
}

template <int CNT, int NEXTCNT>
__device__ __forceinline__ void run_group(
    int g, const float2* __restrict__ xp, float2* __restrict__ op,
    const float* __restrict__ ks, float2 buf[32],
    unsigned WA[6], unsigned WB[6],
    float& v1A, float& v2A, float& rA,
    float& v1B, float& v2B, float& rB)
{
    const float c1    = 1.7235681711139413f;      // a + b   (a=e^-0.2, b=e^-0.1)
    const float c2    = -0.7408182206817179f;     // -ab = -e^-0.3
    const float Ac    = 4.5399929762484854e-05f;  // a^50 = b^100 = e^-10
    const float alpha = 0.9048374180359595f;      // e^-0.1

    // rotate history words, build current group's words from the float buffer
    #pragma unroll
    for (int k = 5; k >= 1; k--) { WA[k] = WA[k - 1]; WB[k] = WB[k - 1]; }
    unsigned cwA = 0u, cwB = 0u;
    #pragma unroll
    for (int i = 0; i < CNT; i++) {
        if (buf[i].x != 0.0f) cwA |= 1u << i;
        if (buf[i].y != 0.0f) cwB |= 1u << i;
    }
    WA[0] = cwA; WB[0] = cwB;

    // prefetch next group while this group computes (~1300 cyc of cover)
    if (NEXTCNT > 0) {
        const float2* p = xp + (size_t)(32 * (g + 1)) * HTBN;
        #pragma unroll
        for (int i = 0; i < NEXTCNT; i++)
            buf[i] = __ldcs(p + (size_t)i * HTBN);
    }

    // composite tap words: bit i = x[32g + i - 50] / x[32g + i - 100]
    const unsigned W50A  = __funnelshift_rc(WA[2], WA[1], 14);
    const unsigned W50B  = __funnelshift_rc(WB[2], WB[1], 14);
    const unsigned W100A = __funnelshift_rc(WA[4], WA[3], 28);
    const unsigned W100B = __funnelshift_rc(WB[4], WB[3], 28);

    float2* o = op + (size_t)(32 * g) * HTBN;

    #pragma unroll
    for (int i = 0; i < CNT; i++) {
        const float xfA = (WA[0] & (1u << i)) ? 1.0f : 0.0f;
        const float xfB = (WB[0] & (1u << i)) ? 1.0f : 0.0f;

        float vA = fmaf(c1, v1A, fmaf(c2, v2A, xfA));
        float vB = fmaf(c1, v1B, fmaf(c2, v2B, xfB));
        vA = (W50A  & (1u << i)) ? vA - Ac : vA;
        vB = (W50B  & (1u << i)) ? vB - Ac : vB;
        vA = (W100A & (1u << i)) ? vA - Ac : vA;
        vB = (W100B & (1u << i)) ? vB - Ac : vB;
        v2A = v1A; v1A = vA;
        v2B = v1B; v1B = vB;

        float uA = vA + rA;
        float uB = vB + rB;
        const bool mA = fabsf(uA - 1.0f) < MARGIN;
        const bool mB = fabsf(uB - 1.0f) < MARGIN;
        if (__builtin_expect(mA || mB, 0)) {       // one branch for both neurons
            if (mA) uA = exact_vmem_w(WA, i, ks) + rA;
            if (mB) uB = exact_vmem_w(WB, i, ks) + rB;
        }

        const float sA = (uA >= 1.0f) ? 1.0f : 0.0f;
        const float sB = (uB >= 1.0f) ? 1.0f : 0.0f;
        rA = (rA - sA) * alpha;
        rB = (rB - sB) * alpha;

        __stcs(o + (size_t)i * HTBN, make_float2(sA, sB));
    }
}

__global__ __launch_bounds__(BLK)
void SpikingLayer_90202903151092_kernel(const float2* __restrict__ x2,
                                        const float* __restrict__ ker,
                                        float2* __restrict__ out2) {
    __shared__ float ks[152];
    for (int i = threadIdx.x; i < 149; i += BLK) ks[i] = ker[i];
    __syncthreads();

    const int np = blockIdx.x * BLK + threadIdx.x;   // neuron pair id (0..32767)
    const float2* xp = x2 + np;
    float2*       op = out2 + np;

    unsigned WA[6] = {0u, 0u, 0u, 0u, 0u, 0u};
    unsigned WB[6] = {0u, 0u, 0u, 0u, 0u, 0u};
    float v1A = 0.0f, v2A = 0.0f, rA = 0.0f;
    float v1B = 0.0f, v2B = 0.0f, rB = 0.0f;

    float2 buf[32];
    #pragma unroll
    for (int i = 0; i < 32; i++)                     // prefetch group 0
        buf[i] = __ldcs(xp + (size_t)i * HTBN);

    #pragma unroll 1
    for (int g = 0; g < 14; g++)
        run_group<32, 32>(g, xp, op, ks, buf, WA, WB, v1A, v2A, rA, v1B, v2B, rB);
    run_group<32, 20>(14, xp, op, ks, buf, WA, WB, v1A, v2A, rA, v1B, v2B, rB);
    run_group<20, 0>(15, xp, op, ks, buf, WA, WB, v1A, v2A, rA, v1B, v2B, rB);
}

extern "C" void kernel_launch(void* const* d_in, const int* in_sizes, int n_in,
                              void* d_out, int out_size) {
    const float* x   = (const float*)d_in[0];  // binary_input (500,16,1,4096) f32
    const float* ker = (const float*)d_in[1];  // epsp_kernel (1,149) f32
    float* out = (float*)d_out;                // spikes (500,16,4096) f32
    SpikingLayer_90202903151092_kernel<<<HTBN / BLK, BLK>>>(
        (const float2*)x, ker, (float2*)out);
}

// round 10
// speedup vs baseline: 1.9067x; 1.9067x over previous
#include <cuda_runtime.h>
#include <math.h>

// SpikingLayer T=500, B*N=65536. Fused, 1 neuron/thread, per-step INLINE margin
// (the only proven-correct shape: R3/R5/R6/R7). Per 32-step group: register
// word history + funnel composites (verified), single-buffer prefetch of the
// next group's floats while computing from word bits.
// Exact path (reference f32 rounding: sum k[j] over set history bits, lag j
// descending 148..0, sequential f32 adds) is software-pipelined (load next tap
// while adding current) -- order unchanged, fp-identical.
// MARGIN = 2e-4: IIR worst-case drift bound 3.5e-5 gives 6x headroom, so all
// decisions outside the margin match the exact path => output identical to the
// R3-class kernels.

#define TBN 65536
#define MARGIN 2e-4f
#define BLK 128

__device__ __forceinline__ float exact_vmem_w(const unsigned W[6], int i,
                                              const float* __restrict__ ks) {
    // W[k] = packed word of group g-k (bit p = x[32*(g-k)+p]); t = 32g + i.
    float acc = 0.0f;
    #pragma unroll
    for (int w = 4; w >= 0; w--) {                 // oldest lag window first
        unsigned win = __funnelshift_rc(W[w + 1], W[w], (unsigned)(i + 1));
        unsigned m = __brev(win);                  // bit b = x[t - 32w - b]
        if (w == 4) m &= 0x001FFFFFu;              // lags <= 148
        if (m) {
            // 2-stage pipeline: LDS of next tap overlaps FADD of current.
            unsigned b = 31u - __clz(m); m &= ~(1u << b);
            float kv = ks[32 * w + b];
            while (m) {
                unsigned b2 = 31u - __clz(m); m &= ~(1u << b2);
                float kv2 = ks[32 * w + b2];
                acc += kv;                         // descending-lag order kept
                kv = kv2;
            }
            acc += kv;
        }
    }
    return acc;
}

template <int CNT, int NEXTCNT>
__device__ __forceinline__ void run_group(
    int g, const float* __restrict__ xp, float* __restrict__ op,
    const float* __restrict__ ks, float buf[32], unsigned W[6],
    float& v1, float& v2, float& r)
{
    const float c1    = 1.7235681711139413f;      // a + b   (a=e^-0.2, b=e^-0.1)
    const float c2    = -0.7408182206817179f;     // -ab = -e^-0.3
    const float A     = 4.5399929762484854e-05f;  // a^50 = b^100 = e^-10
    const float alpha = 0.9048374180359595f;      // e^-0.1

    // rotate history, build this group's packed word from the loaded floats
    #pragma unroll
    for (int k = 5; k >= 1; k--) W[k] = W[k - 1];
    unsigned cw = 0u;
    #pragma unroll
    for (int i = 0; i < CNT; i++)
        cw |= (buf[i] != 0.0f) ? (1u << i) : 0u;
    W[0] = cw;

    // prefetch next group into buf (compute below reads word bits, not buf)
    if (NEXTCNT > 0) {
        const float* p = xp + (size_t)(32 * (g + 1)) * TBN;
        #pragma unroll
        for (int i = 0; i < NEXTCNT; i++)
            buf[i] = __ldcs(p + (size_t)i * TBN);
    }

    // composite tap words: bit i = x[32g + i - 50] / x[32g + i - 100]
    const unsigned W50  = __funnelshift_rc(W[2], W[1], 14);
    const unsigned W100 = __funnelshift_rc(W[4], W[3], 28);

    float* o = op + (size_t)(32 * g) * TBN;

    #pragma unroll
    for (int i = 0; i < CNT; i++) {
        const float xf = (W[0] & (1u << i)) ? 1.0f : 0.0f;

        float v = fmaf(c1, v1, fmaf(c2, v2, xf));
        v = (W50  & (1u << i)) ? v - A : v;       // x[t-50]
        v = (W100 & (1u << i)) ? v - A : v;       // x[t-100]
        v2 = v1; v1 = v;

        float u = v + r;
        if (__builtin_expect(fabsf(u - 1.0f) < MARGIN, 0))
            u = exact_vmem_w(W, i, ks) + r;       // reference f32 rounding

        const float s = (u >= 1.0f) ? 1.0f : 0.0f;
        r = (r - s) * alpha;
        __stcs(o + (size_t)i * TBN, s);
    }
}

__global__ __launch_bounds__(BLK)
void SpikingLayer_90202903151092_kernel(const float* __restrict__ x,
                                        const float* __restrict__ ker,
                                        float* __restrict__ out) {
    __shared__ float ks[152];
    for (int i = threadIdx.x; i < 149; i += BLK) ks[i] = ker[i];
    __syncthreads();

    const int n = blockIdx.x * BLK + threadIdx.x;      // neuron id
    const float* xp = x + n;
    float*       op = out + n;

    unsigned W[6] = {0u, 0u, 0u, 0u, 0u, 0u};
    float v1 = 0.0f, v2 = 0.0f, r = 0.0f;

    float buf[32];
    #pragma unroll
    for (int i = 0; i < 32; i++)                       // load group 0
        buf[i] = __ldcs(xp + (size_t)i * TBN);

    #pragma unroll 1
    for (int g = 0; g < 14; g++)
        run_group<32, 32>(g, xp, op, ks, buf, W, v1, v2, r);
    run_group<32, 20>(14, xp, op, ks, buf, W, v1, v2, r);
    run_group<20, 0>(15, xp, op, ks, buf, W, v1, v2, r);   // t = 480..499
}

extern "C" void kernel_launch(void* const* d_in, const int* in_sizes, int n_in,
                              void* d_out, int out_size) {
    const float* x   = (const float*)d_in[0];  // binary_input (500,16,1,4096) f32
    const float* ker = (const float*)d_in[1];  // epsp_kernel (1,149) f32
    float* out = (float*)d_out;                // spikes (500,16,4096) f32
    SpikingLayer_90202903151092_kernel<<<TBN / BLK, BLK>>>(x, ker, out);
}

// round 14
// speedup vs baseline: 2.3390x; 1.2267x over previous
#include <cuda_runtime.h>
#include <math.h>

// SpikingLayer T=500, B*N=65536. This is the R3 passing kernel (82.4us,
// rel_err 0.0007257581) with EXACTLY two proven-safe changes:
//  1. MARGIN 1e-3 -> 2e-4  (validated by R10 passing with 2e-4: committed
//     trajectory arithmetic identical => identical decisions)
//  2. pipelined exact bit-loop (validated by R10: same descending-lag
//     sequential f32 summation order, only load/add overlap)
// ALL committed per-step arithmetic is byte-identical to R3. The
// spec/replay and algebraic-rewrite frontiers are closed (3 identical
// failures); do not touch the trajectory ops.

#define TBN 65536
#define T_STEPS 500
#define UF 20       // 500 = 25 * 20
#define BLK 64
#define MARGIN 2e-4f

__global__ __launch_bounds__(BLK)
void SpikingLayer_90202903151092_kernel(const float* __restrict__ x,
                                        const float* __restrict__ ker,
                                        float* __restrict__ out) {
    __shared__ float ks[152];
    for (int i = threadIdx.x; i < 149; i += BLK) ks[i] = ker[i];
    __syncthreads();

    const int idx = blockIdx.x * BLK + threadIdx.x;   // neuron id
    const float* xp = x + idx;
    float*       op = out + idx;

    const float c1    = 1.7235681711139413f;    // a + b   (a=e^-0.2, b=e^-0.1)
    const float c2    = -0.7408182206817179f;   // -ab = -e^-0.3
    const float A     = 4.5399929762484854e-05f;// a^50 = b^100 = e^-10
    const float alpha = 0.9048374180359595f;    // e^-0.1 (refractory decay)

    // 160-bit spike history: bit j = x[t - j] after the shift (j <= 148 kept)
    unsigned h0 = 0u, h1 = 0u, h2 = 0u, h3 = 0u, h4 = 0u;
    float v1 = 0.0f, v2 = 0.0f, r = 0.0f;

    #pragma unroll 1
    for (int t0 = 0; t0 < T_STEPS; t0 += UF) {
        // front-batched streaming loads: 20 independent LDGs in flight
        float xv[UF];
        #pragma unroll
        for (int i = 0; i < UF; i++)
            xv[i] = __ldcs(xp + (size_t)(t0 + i) * TBN);

        #pragma unroll
        for (int i = 0; i < UF; i++) {
            unsigned nb = (xv[i] != 0.0f) ? 1u : 0u;
            h4 = ((h4 << 1) | (h3 >> 31)) & 0x001FFFFFu;
            h3 = (h3 << 1) | (h2 >> 31);
            h2 = (h2 << 1) | (h1 >> 31);
            h1 = (h1 << 1) | (h0 >> 31);
            h0 = (h0 << 1) | nb;

            // IIR approx of the conv (error ~1e-5 << MARGIN)
            float v = fmaf(c1, v1, fmaf(c2, v2, xv[i]));
            v -= (h1 & (1u << 18)) ? A : 0.0f;   // x[t-50]
            v -= (h3 & (1u << 4))  ? A : 0.0f;   // x[t-100]
            v2 = v1; v1 = v;

            float u = v + r;
            if (__builtin_expect(fabsf(u - 1.0f) < MARGIN, 0)) {
                // near threshold: recompute with the reference's exact f32
                // rounding — sum ks[j] over set bits, j descending 148..0,
                // sequential adds. 2-stage pipeline (load next tap while
                // adding current) keeps the order identical.
                float acc = 0.0f;
                unsigned words[5] = {h0, h1, h2, h3, h4};
                #pragma unroll
                for (int w = 4; w >= 0; w--) {
                    unsigned m = words[w];
                    if (m) {
                        unsigned b = 31u - __clz(m); m &= ~(1u << b);
                        float kv = ks[32 * w + b];
                        while (m) {
                            unsigned b2 = 31u - __clz(m); m &= ~(1u << b2);
                            float kv2 = ks[32 * w + b2];
                            acc += kv;            // descending-lag order kept
                            kv = kv2;
                        }
                        acc += kv;
                    }
                }
                u = acc + r;
            }

            // committed per-step arithmetic: FROZEN (R3 form)
            float s = (u >= 1.0f) ? 1.0f : 0.0f;
            r = (r - s) * alpha;
            __stcs(op + (size_t)(t0 + i) * TBN, s);
        }
    }
}

extern "C" void kernel_launch(void* const* d_in, const int* in_sizes, int n_in,
                              void* d_out, int out_size) {
    const float* x   = (const float*)d_in[0];  // binary_input (500,16,1,4096) f32
    const float* ker = (const float*)d_in[1];  // epsp_kernel (1,149) f32
    float* out = (float*)d_out;                // spikes (500,16,4096) f32
    SpikingLayer_90202903151092_kernel<<<TBN / BLK, BLK>>>(x, ker, out);
}

// round 17
// speedup vs baseline: 2.8193x; 1.2053x over previous
#include <cuda_runtime.h>
#include <math.h>

// SpikingLayer T=500, B*N=65536. R15 architecture with the ONE bug fixed:
// group words G1..G5 must be ASCENDING (bit p = x[32g+p]) for the funnel
// composites + exact windows; h0 is a newest-first shift register, so the
// boundary rotation needs G1 = __brev(h0)  (R15 wrote G1 = h0 -> garbage taps).
//  - h0: only per-step shift register (bit p = x[t-p]); G1..G5 rotated per group
//  - lag-50/100 taps via R6/R10-validated ascending-word composites
//  - exact path __noinline__: windows w=4..1 funnel+brev from G words
//    (R10-validated), w=0 from h0 (R14-validated); identical w=4..0,
//    descending-lag sequential f32 order (reference conv rounding)
//  - committed per-step arithmetic byte-identical to R14 (FROZEN)
// MARGIN = 2e-4 (R10/R14-validated).

#define TBN 65536
#define BLK 64
#define MARGIN 2e-4f

__device__ __noinline__ float exact_vmem(unsigned h0, unsigned G1, unsigned G2,
                                         unsigned G3, unsigned G4, unsigned G5,
                                         int i, const float* __restrict__ ks) {
    const unsigned G[6] = {0u, G1, G2, G3, G4, G5};   // G[k] = word of group g-k
    float acc = 0.0f;
    // windows w = 4..1 (lags 32w..32w+31), oldest first
    #pragma unroll
    for (int w = 4; w >= 1; w--) {
        unsigned win = __funnelshift_rc(G[w + 1], G[w], (unsigned)(i + 1));
        unsigned m = __brev(win);                     // bit b = x[t - 32w - b]
        if (w == 4) m &= 0x001FFFFFu;                 // lags <= 148
        if (m) {                                      // descending lag, pipelined
            unsigned b = 31u - __clz(m); m &= ~(1u << b);
            float kv = ks[32 * w + b];
            while (m) {
                unsigned b2 = 31u - __clz(m); m &= ~(1u << b2);
                float kv2 = ks[32 * w + b2];
                acc += kv;
                kv = kv2;
            }
            acc += kv;
        }
    }
    // window w = 0: h0 bit p = x[t - p] (newest-first convention, as in R14)
    {
        unsigned m = h0;
        if (m) {
            unsigned b = 31u - __clz(m); m &= ~(1u << b);
            float kv = ks[b];
            while (m) {
                unsigned b2 = 31u - __clz(m); m &= ~(1u << b2);
                float kv2 = ks[b2];
                acc += kv;
                kv = kv2;
            }
            acc += kv;
        }
    }
    return acc;
}

template <int CNT>
__device__ __forceinline__ void run_group(
    int g, const float* __restrict__ xp, float* __restrict__ op,
    const float* __restrict__ ks, unsigned& h0,
    unsigned& G1, unsigned& G2, unsigned& G3, unsigned& G4, unsigned& G5,
    float& v1, float& v2, float& r)
{
    const float c1    = 1.7235681711139413f;      // a + b   (a=e^-0.2, b=e^-0.1)
    const float c2    = -0.7408182206817179f;     // -ab = -e^-0.3
    const float A     = 4.5399929762484854e-05f;  // a^50 = b^100 = e^-10
    const float alpha = 0.9048374180359595f;      // e^-0.1

    // front-batched streaming loads; compute consumes xv[i] incrementally
    float xv[CNT];
    const float* p = xp + (size_t)(32 * g) * TBN;
    #pragma unroll
    for (int i = 0; i < CNT; i++)
        xv[i] = __ldcs(p + (size_t)i * TBN);

    // composite tap words (ascending G words): bit i = x[32g+i-50] / x[32g+i-100]
    const unsigned W50  = __funnelshift_rc(G2, G1, 14);
    const unsigned W100 = __funnelshift_rc(G4, G3, 28);

    float* o = op + (size_t)(32 * g) * TBN;

    #pragma unroll
    for (int i = 0; i < CNT; i++) {
        h0 = (h0 << 1) | ((xv[i] != 0.0f) ? 1u : 0u);

        // committed arithmetic: FROZEN (R14 form)
        float v = fmaf(c1, v1, fmaf(c2, v2, xv[i]));
        v -= (W50  & (1u << i)) ? A : 0.0f;       // x[t-50]
        v -= (W100 & (1u << i)) ? A : 0.0f;       // x[t-100]
        v2 = v1; v1 = v;

        float u = v + r;
        if (__builtin_expect(fabsf(u - 1.0f) < MARGIN, 0))
            u = exact_vmem(h0, G1, G2, G3, G4, G5, i, ks) + r;

        float s = (u >= 1.0f) ? 1.0f : 0.0f;
        r = (r - s) * alpha;
        __stcs(o + (size_t)i * TBN, s);
    }

    // group boundary: h0 holds this group's bits newest-first; store ASCENDING
    if (CNT == 32) {
        G5 = G4; G4 = G3; G3 = G2; G2 = G1; G1 = __brev(h0);
    }
}

__global__ __launch_bounds__(BLK, 7)
void SpikingLayer_90202903151092_kernel(const float* __restrict__ x,
                                        const float* __restrict__ ker,
                                        float* __restrict__ out) {
    __shared__ float ks[152];
    for (int i = threadIdx.x; i < 149; i += BLK) ks[i] = ker[i];
    __syncthreads();

    const int n = blockIdx.x * BLK + threadIdx.x;      // neuron id
    const float* xp = x + n;
    float*       op = out + n;

    unsigned h0 = 0u, G1 = 0u, G2 = 0u, G3 = 0u, G4 = 0u, G5 = 0u;
    float v1 = 0.0f, v2 = 0.0f, r = 0.0f;

    #pragma unroll 1
    for (int g = 0; g < 15; g++)
        run_group<32>(g, xp, op, ks, h0, G1, G2, G3, G4, G5, v1, v2, r);
    run_group<20>(15, xp, op, ks, h0, G1, G2, G3, G4, G5, v1, v2, r);  // t=480..499
}

extern "C" void kernel_launch(void* const* d_in, const int* in_sizes, int n_in,
                              void* d_out, int out_size) {
    const float* x   = (const float*)d_in[0];  // binary_input (500,16,1,4096) f32
    const float* ker = (const float*)d_in[1];  // epsp_kernel (1,149) f32
    float* out = (float*)d_out;                // spikes (500,16,4096) f32
    SpikingLayer_90202903151092_kernel<<<TBN / BLK, BLK>>>(x, ker, out);
}